// round 6
// baseline (speedup 1.0000x reference)
#include <cuda_runtime.h>
#include <math.h>
#include <stdint.h>

#define BATCH 4
#define SEQ   1024
#define DM    1024
#define NH    16
#define DH    64

// Scratch (device globals — no allocation allowed)
__device__ float g_q[(size_t)BATCH*NH*SEQ*DH];   // [b*NH+h][s][d]
__device__ float g_k[(size_t)BATCH*SEQ*DH];      // [b*S+s][d]
__device__ float g_v[(size_t)BATCH*SEQ*DH];
__device__ float g_ctx[(size_t)BATCH*SEQ*DM];    // [b*S+s][h*DH+d]

// ---------------------------------------------------------------------------
// TF32 helpers
// ---------------------------------------------------------------------------
__device__ __forceinline__ float f2tf(float x) {
    uint32_t u;
    asm("cvt.rna.tf32.f32 %0, %1;" : "=r"(u) : "f"(x));
    return __uint_as_float(u);
}

__device__ __forceinline__ void mma_tf32(float* c, const uint32_t* a, const uint32_t* b) {
    asm volatile(
        "mma.sync.aligned.m16n8k8.row.col.f32.tf32.tf32.f32 "
        "{%0,%1,%2,%3}, {%4,%5,%6,%7}, {%8,%9}, {%0,%1,%2,%3};\n"
        : "+f"(c[0]), "+f"(c[1]), "+f"(c[2]), "+f"(c[3])
        : "r"(a[0]), "r"(a[1]), "r"(a[2]), "r"(a[3]), "r"(b[0]), "r"(b[1]));
}

__device__ __forceinline__ void l2_prefetch(const void* p) {
    asm volatile("prefetch.global.L2 [%0];" :: "l"(p));
}

// ---------------------------------------------------------------------------
// TF32 GEMM: C = A @ B^T (+bias). A[M,K] rm, B[N,K] rm. (unchanged from R4)
// ---------------------------------------------------------------------------
#define GP 20

template<int MODE>
__global__ __launch_bounds__(256, 2)
void gemm_tf32(const float* __restrict__ A, const float* __restrict__ B,
               const float* __restrict__ bias, float* __restrict__ C,
               int M, int N, int K)
{
    __shared__ float sA[128 * GP];
    __shared__ float sB[128 * GP];

    const int tid  = threadIdx.x;
    const int lane = tid & 31;
    const int w    = tid >> 5;
    const int wr   = w >> 1;
    const int wc   = w & 1;
    const int g    = lane >> 2;
    const int t    = lane & 3;
    const int m0   = blockIdx.y * 128;
    const int n0   = blockIdx.x * 128;

    const int ldr = tid >> 2;
    const int ldc = (tid & 3) * 4;

    float acc[2][8][4];
    #pragma unroll
    for (int mt = 0; mt < 2; mt++)
        #pragma unroll
        for (int nt = 0; nt < 8; nt++)
            #pragma unroll
            for (int q = 0; q < 4; q++) acc[mt][nt][q] = 0.f;

    float4 ar[2], br[2];
    #pragma unroll
    for (int h = 0; h < 2; h++) {
        const int row = ldr + h * 64;
        ar[h] = *(const float4*)&A[(size_t)(m0 + row) * K + ldc];
        br[h] = make_float4(0.f, 0.f, 0.f, 0.f);
        if (n0 + row < N)
            br[h] = *(const float4*)&B[(size_t)(n0 + row) * K + ldc];
    }

    for (int k0 = 0; k0 < K; k0 += 16) {
        #pragma unroll
        for (int h = 0; h < 2; h++) {
            const int row = ldr + h * 64;
            float* da = &sA[row * GP + ldc];
            da[0] = f2tf(ar[h].x); da[1] = f2tf(ar[h].y);
            da[2] = f2tf(ar[h].z); da[3] = f2tf(ar[h].w);
            float* db = &sB[row * GP + ldc];
            db[0] = f2tf(br[h].x); db[1] = f2tf(br[h].y);
            db[2] = f2tf(br[h].z); db[3] = f2tf(br[h].w);
        }
        if (k0 + 16 < K) {
            #pragma unroll
            for (int h = 0; h < 2; h++) {
                const int row = ldr + h * 64;
                ar[h] = *(const float4*)&A[(size_t)(m0 + row) * K + k0 + 16 + ldc];
                if (n0 + row < N)
                    br[h] = *(const float4*)&B[(size_t)(n0 + row) * K + k0 + 16 + ldc];
                else
                    br[h] = make_float4(0.f, 0.f, 0.f, 0.f);
            }
        }
        __syncthreads();

        #pragma unroll
        for (int ks = 0; ks < 2; ks++) {
            const int k = ks * 8;
            uint32_t af[2][4], bf[8][2];
            #pragma unroll
            for (int mt = 0; mt < 2; mt++) {
                const int mr = wr * 32 + mt * 16;
                af[mt][0] = __float_as_uint(sA[(mr + g) * GP + k + t]);
                af[mt][1] = __float_as_uint(sA[(mr + g + 8) * GP + k + t]);
                af[mt][2] = __float_as_uint(sA[(mr + g) * GP + k + t + 4]);
                af[mt][3] = __float_as_uint(sA[(mr + g + 8) * GP + k + t + 4]);
            }
            #pragma unroll
            for (int nt = 0; nt < 8; nt++) {
                const int nn = wc * 64 + nt * 8 + g;
                bf[nt][0] = __float_as_uint(sB[nn * GP + k + t]);
                bf[nt][1] = __float_as_uint(sB[nn * GP + k + t + 4]);
            }
            #pragma unroll
            for (int mt = 0; mt < 2; mt++)
                #pragma unroll
                for (int nt = 0; nt < 8; nt++)
                    mma_tf32(acc[mt][nt], af[mt], bf[nt]);
        }
        __syncthreads();
    }

    #pragma unroll
    for (int mt = 0; mt < 2; mt++) {
        #pragma unroll
        for (int rr = 0; rr < 2; rr++) {
            const int m = m0 + wr * 32 + mt * 16 + g + rr * 8;
            #pragma unroll
            for (int nt = 0; nt < 8; nt++) {
                const int n = n0 + wc * 64 + nt * 8 + 2 * t;
                const float v0 = acc[mt][nt][rr * 2 + 0];
                const float v1 = acc[mt][nt][rr * 2 + 1];
                if (MODE == 0) {
                    if (n < N) *(float2*)&C[(size_t)m * N + n] = make_float2(v0, v1);
                } else if (MODE == 1) {
                    const int b = m >> 10, s = m & 1023;
                    const int h = n >> 6, d = n & 63;
                    *(float2*)&C[(((size_t)(b * NH + h)) * SEQ + s) * DH + d] =
                        make_float2(v0, v1);
                } else {
                    *(float2*)&C[(size_t)m * N + n] =
                        make_float2(v0 + bias[n], v1 + bias[n + 1]);
                }
            }
        }
    }
}

// ---------------------------------------------------------------------------
// Fused attention, in-register softmax. One CTA per query index i.
// 8 warps: warp (b, half). Scores kept in C-frags; quad shfl reductions;
// cross-half exchange of 16 floats; AV k-split per warp over its j-half.
// ---------------------------------------------------------------------------
#define AP 68

#define SM_Q   (DH * AP)               // actually [r=64][AP]
#define SM_KR  (4 * 64 * AP)           // KR tiles / V tiles / epilogue partials
#define SM_ATTN_FLOATS (SM_Q + SM_KR + 2 * 128)
#define SM_ATTN_BYTES  (SM_ATTN_FLOATS * 4)

__global__ __launch_bounds__(256, 2)
void attn_kernel(const float* __restrict__ rel,
                 const float* __restrict__ qb,
                 const float* __restrict__ kb,
                 const float* __restrict__ vb,
                 float* __restrict__ ctx)
{
    extern __shared__ float sm[];
    float* sQ   = sm;                  // [64][AP] tf32 Q rows
    float* sKR  = sQ + SM_Q;           // [b][64][AP]: KR (scores) / V^T (AV) / partials
    float* sExM = sKR + SM_KR;         // [8 warps][16 rows] max exchange
    float* sExS = sExM + 128;          // [8 warps][16 rows] sum exchange

    const int i    = blockIdx.x;
    const int tid  = threadIdx.x;
    const int lane = tid & 31;
    const int w    = tid >> 5;
    const int b    = w >> 1;           // batch
    const int half = w & 1;            // j-half of this warp
    const int g    = lane >> 2;
    const int t    = lane & 3;
    const unsigned FULL = 0xffffffffu;

    // Load Q for all 64 (b,h) rows at query i (tf32)
    #pragma unroll
    for (int tix = 0; tix < 16; tix++) {
        const int idx = tix * 256 + tid;
        const int r = idx >> 6, d = idx & 63;
        sQ[r * AP + d] = f2tf(qb[((size_t)r * SEQ + i) * DH + d]);
    }

    // per-warp running softmax state (rows g and g+8 of batch b)
    float mr0 = -INFINITY, mr1 = -INFINITY, lr0 = 0.f, lr1 = 0.f;
    float cacc[8][4];
    #pragma unroll
    for (int nt = 0; nt < 8; nt++)
        #pragma unroll
        for (int q = 0; q < 4; q++) cacc[nt][q] = 0.f;

    for (int j0 = 0; j0 < SEQ; j0 += 64) {
        __syncthreads();   // S_top: prev tile's V reads done before overwrite

        // ---- build KR[b][j][d] = tf32(K + rel) ----
        #pragma unroll
        for (int tix = 0; tix < 4; tix++) {
            const int idx = tix * 256 + tid;
            const int j  = idx >> 4;
            const int d4 = (idx & 15) * 4;
            const float4 rv = *(const float4*)&rel[((size_t)i * SEQ + j0 + j) * DH + d4];
            if (j0 + 64 < SEQ && (idx & 7) == 0)
                l2_prefetch(&rel[((size_t)i * SEQ + j0 + 64 + j) * DH + d4]);
            #pragma unroll
            for (int bb = 0; bb < 4; bb++) {
                const float4 k4 = *(const float4*)&kb[((size_t)(bb * SEQ) + j0 + j) * DH + d4];
                float4 o;
                o.x = f2tf(k4.x + rv.x); o.y = f2tf(k4.y + rv.y);
                o.z = f2tf(k4.z + rv.z); o.w = f2tf(k4.w + rv.w);
                *(float4*)&sKR[(bb * 64 + j) * AP + d4] = o;
            }
        }
        __syncthreads();   // S1

        // ---- scores MMA: rows b*16+{g,g+8}, cols half*32 + nt*8 + {2t,2t+1} ----
        float pr[4][4];
        #pragma unroll
        for (int nt = 0; nt < 4; nt++)
            #pragma unroll
            for (int q = 0; q < 4; q++) pr[nt][q] = 0.f;

        #pragma unroll
        for (int ks = 0; ks < 8; ks++) {
            const int k = ks * 8;
            uint32_t af[4], bf[2];
            af[0] = __float_as_uint(sQ[(b * 16 + g) * AP + k + t]);
            af[1] = __float_as_uint(sQ[(b * 16 + g + 8) * AP + k + t]);
            af[2] = __float_as_uint(sQ[(b * 16 + g) * AP + k + t + 4]);
            af[3] = __float_as_uint(sQ[(b * 16 + g + 8) * AP + k + t + 4]);
            #pragma unroll
            for (int nt = 0; nt < 4; nt++) {
                const int n = half * 32 + nt * 8 + g;
                bf[0] = __float_as_uint(sKR[(b * 64 + n) * AP + k + t]);
                bf[1] = __float_as_uint(sKR[(b * 64 + n) * AP + k + t + 4]);
                mma_tf32(pr[nt], af, bf);
            }
        }

        // ---- in-register row max (quad reduce) + cross-half exchange ----
        float m0 = -INFINITY, m1 = -INFINITY;
        #pragma unroll
        for (int nt = 0; nt < 4; nt++) {
            m0 = fmaxf(m0, fmaxf(pr[nt][0], pr[nt][1]));
            m1 = fmaxf(m1, fmaxf(pr[nt][2], pr[nt][3]));
        }
        m0 = fmaxf(m0, __shfl_xor_sync(FULL, m0, 1));
        m0 = fmaxf(m0, __shfl_xor_sync(FULL, m0, 2));
        m1 = fmaxf(m1, __shfl_xor_sync(FULL, m1, 1));
        m1 = fmaxf(m1, __shfl_xor_sync(FULL, m1, 2));
        if (t == 0) {
            sExM[w * 16 + g]     = m0;
            sExM[w * 16 + 8 + g] = m1;
        }
        __syncthreads();   // S2 (also: all scores reads of sKR complete)

        const float pm0 = sExM[(w ^ 1) * 16 + g];
        const float pm1 = sExM[(w ^ 1) * 16 + 8 + g];
        const float mn0 = fmaxf(mr0, 0.125f * fmaxf(m0, pm0));
        const float mn1 = fmaxf(mr1, 0.125f * fmaxf(m1, pm1));
        const float corr0 = __expf(mr0 - mn0);
        const float corr1 = __expf(mr1 - mn1);
        mr0 = mn0; mr1 = mn1;

        // ---- exp + row sums in registers ----
        float s0 = 0.f, s1 = 0.f;
        #pragma unroll
        for (int nt = 0; nt < 4; nt++) {
            float p0 = __expf(0.125f * pr[nt][0] - mn0);
            float p1 = __expf(0.125f * pr[nt][1] - mn0);
            float p2 = __expf(0.125f * pr[nt][2] - mn1);
            float p3 = __expf(0.125f * pr[nt][3] - mn1);
            s0 += p0 + p1; s1 += p2 + p3;
            pr[nt][0] = f2tf(p0); pr[nt][1] = f2tf(p1);
            pr[nt][2] = f2tf(p2); pr[nt][3] = f2tf(p3);
        }
        s0 += __shfl_xor_sync(FULL, s0, 1);
        s0 += __shfl_xor_sync(FULL, s0, 2);
        s1 += __shfl_xor_sync(FULL, s1, 1);
        s1 += __shfl_xor_sync(FULL, s1, 2);
        if (t == 0) {
            sExS[w * 16 + g]     = s0;
            sExS[w * 16 + 8 + g] = s1;
        }

        // ---- V: gmem [b][j][d] -> sV[b][d][j] (tf32), 2-way pattern ----
        #pragma unroll
        for (int tix = 0; tix < 4; tix++) {
            const int idx = tix * 256 + tid;
            const int j  = idx >> 4;
            const int db = idx & 15;
            #pragma unroll
            for (int bb = 0; bb < 4; bb++) {
                const float* vrow = &vb[((size_t)(bb * SEQ) + j0 + j) * DH];
                #pragma unroll
                for (int s = 0; s < 4; s++) {
                    const int d = db + 16 * s;
                    sKR[(bb * 64 + d) * AP + j] = f2tf(vrow[d]);
                }
            }
        }
        __syncthreads();   // S3

        lr0 = lr0 * corr0 + s0 + sExS[(w ^ 1) * 16 + g];
        lr1 = lr1 * corr1 + s1 + sExS[(w ^ 1) * 16 + 8 + g];

        // ---- rescale partial ctx + AV over own j-half (k=32), all 64 d ----
        #pragma unroll
        for (int nt = 0; nt < 8; nt++) {
            cacc[nt][0] *= corr0; cacc[nt][1] *= corr0;
            cacc[nt][2] *= corr1; cacc[nt][3] *= corr1;
        }
        #pragma unroll
        for (int ks = 0; ks < 4; ks++) {
            // P C-frag -> A-frag via quad shuffles:
            // P[row][8*ks+tt] lives at lane 4g+(tt>>1), reg parity tt&1.
            const int src0 = 4 * g + (t >> 1);
            uint32_t af[4];
            {
                float u0 = __shfl_sync(FULL, pr[ks][0], src0);
                float u1 = __shfl_sync(FULL, pr[ks][1], src0);
                float u2 = __shfl_sync(FULL, pr[ks][0], src0 + 2);
                float u3 = __shfl_sync(FULL, pr[ks][1], src0 + 2);
                af[0] = __float_as_uint((t & 1) ? u1 : u0);
                af[2] = __float_as_uint((t & 1) ? u3 : u2);
                float v0 = __shfl_sync(FULL, pr[ks][2], src0);
                float v1 = __shfl_sync(FULL, pr[ks][3], src0);
                float v2 = __shfl_sync(FULL, pr[ks][2], src0 + 2);
                float v3 = __shfl_sync(FULL, pr[ks][3], src0 + 2);
                af[1] = __float_as_uint((t & 1) ? v1 : v0);
                af[3] = __float_as_uint((t & 1) ? v3 : v2);
            }
            const int jl = half * 32 + ks * 8;
            #pragma unroll
            for (int nt = 0; nt < 8; nt++) {
                const int n = nt * 8 + g;          // d column
                uint32_t bf[2];
                bf[0] = __float_as_uint(sKR[(b * 64 + n) * AP + jl + t]);
                bf[1] = __float_as_uint(sKR[(b * 64 + n) * AP + jl + t + 4]);
                mma_tf32(cacc[nt], af, bf);
            }
        }
    }

    // ---- epilogue: combine the two j-half partials, normalize, write ----
    __syncthreads();
    if (half == 1) {
        float* dst = &sKR[b * 1024];
        #pragma unroll
        for (int nt = 0; nt < 8; nt++) {
            *(float2*)&dst[g * 64 + nt * 8 + 2 * t] =
                make_float2(cacc[nt][0], cacc[nt][1]);
            *(float2*)&dst[(g + 8) * 64 + nt * 8 + 2 * t] =
                make_float2(cacc[nt][2], cacc[nt][3]);
        }
    }
    __syncthreads();
    if (half == 0) {
        const float inv0 = 1.f / lr0;
        const float inv1 = 1.f / lr1;
        const float* src = &sKR[b * 1024];
        const size_t base = ((size_t)(b * SEQ) + i) * DM;
        #pragma unroll
        for (int nt = 0; nt < 8; nt++) {
            const int c = nt * 8 + 2 * t;
            float2 p0 = *(const float2*)&src[g * 64 + c];
            float2 p1 = *(const float2*)&src[(g + 8) * 64 + c];
            *(float2*)&ctx[base + g * DH + c] =
                make_float2((cacc[nt][0] + p0.x) * inv0,
                            (cacc[nt][1] + p0.y) * inv0);
            *(float2*)&ctx[base + (g + 8) * DH + c] =
                make_float2((cacc[nt][2] + p1.x) * inv1,
                            (cacc[nt][3] + p1.y) * inv1);
        }
    }
}

// ---------------------------------------------------------------------------
extern "C" void kernel_launch(void* const* d_in, const int* in_sizes, int n_in,
                              void* d_out, int out_size)
{
    const float* x   = (const float*)d_in[0];
    const float* rel = (const float*)d_in[1];
    const float* Wq  = (const float*)d_in[2];
    const float* Wk  = (const float*)d_in[3];
    const float* Wv  = (const float*)d_in[4];
    const float* Wo  = (const float*)d_in[5];
    const float* bo  = (const float*)d_in[6];
    float* out = (float*)d_out;

    float *qb, *kb, *vb, *ctx;
    cudaGetSymbolAddress((void**)&qb,  g_q);
    cudaGetSymbolAddress((void**)&kb,  g_k);
    cudaGetSymbolAddress((void**)&vb,  g_v);
    cudaGetSymbolAddress((void**)&ctx, g_ctx);

    cudaFuncSetAttribute(attn_kernel,
                         cudaFuncAttributeMaxDynamicSharedMemorySize,
                         SM_ATTN_BYTES);

    const int M = BATCH * SEQ;  // 4096

    // q = x @ Wq^T -> [b,h,s,d]
    {
        dim3 grid(DM / 128, M / 128);
        gemm_tf32<1><<<grid, 256>>>(x, Wq, nullptr, qb, M, DM, DM);
    }
    // k, v = x @ Wk^T, x @ Wv^T -> [b*s, 64]
    {
        dim3 grid(1, M / 128);
        gemm_tf32<0><<<grid, 256>>>(x, Wk, nullptr, kb, M, DH, DM);
        gemm_tf32<0><<<grid, 256>>>(x, Wv, nullptr, vb, M, DH, DM);
    }
    // fused attention
    attn_kernel<<<SEQ, 256, SM_ATTN_BYTES>>>(rel, qb, kb, vb, ctx);

    // out = ctx @ Wo^T + bo
    {
        dim3 grid(DM / 128, M / 128);
        gemm_tf32<2><<<grid, 256>>>(ctx, Wo, bo, out, M, DM, DM);
    }
}

// round 7
// speedup vs baseline: 1.5839x; 1.5839x over previous
#include <cuda_runtime.h>
#include <math.h>
#include <stdint.h>

#define BATCH 4
#define SEQ   1024
#define DM    1024
#define NH    16
#define DH    64

// Scratch (device globals — no allocation allowed)
__device__ float g_q[(size_t)BATCH*NH*SEQ*DH];   // [b*NH+h][s][d]
__device__ float g_k[(size_t)BATCH*SEQ*DH];      // [b*S+s][d]
__device__ float g_v[(size_t)BATCH*SEQ*DH];
__device__ float g_ctx[(size_t)BATCH*SEQ*DM];    // [b*S+s][h*DH+d]

// ---------------------------------------------------------------------------
// TF32 helpers
// ---------------------------------------------------------------------------
__device__ __forceinline__ float f2tf(float x) {
    uint32_t u;
    asm("cvt.rna.tf32.f32 %0, %1;" : "=r"(u) : "f"(x));
    return __uint_as_float(u);
}

__device__ __forceinline__ void mma_tf32(float* c, const uint32_t* a, const uint32_t* b) {
    asm volatile(
        "mma.sync.aligned.m16n8k8.row.col.f32.tf32.tf32.f32 "
        "{%0,%1,%2,%3}, {%4,%5,%6,%7}, {%8,%9}, {%0,%1,%2,%3};\n"
        : "+f"(c[0]), "+f"(c[1]), "+f"(c[2]), "+f"(c[3])
        : "r"(a[0]), "r"(a[1]), "r"(a[2]), "r"(a[3]), "r"(b[0]), "r"(b[1]));
}

__device__ __forceinline__ void l2_prefetch(const void* p) {
    asm volatile("prefetch.global.L2 [%0];" :: "l"(p));
}

// ---------------------------------------------------------------------------
// TF32 GEMM: C = A @ B^T (+bias). A[M,K] rm, B[N,K] rm. (R4, unchanged)
// ---------------------------------------------------------------------------
#define GP 20

template<int MODE>
__global__ __launch_bounds__(256, 2)
void gemm_tf32(const float* __restrict__ A, const float* __restrict__ B,
               const float* __restrict__ bias, float* __restrict__ C,
               int M, int N, int K)
{
    __shared__ float sA[128 * GP];
    __shared__ float sB[128 * GP];

    const int tid  = threadIdx.x;
    const int lane = tid & 31;
    const int w    = tid >> 5;
    const int wr   = w >> 1;
    const int wc   = w & 1;
    const int g    = lane >> 2;
    const int t    = lane & 3;
    const int m0   = blockIdx.y * 128;
    const int n0   = blockIdx.x * 128;

    const int ldr = tid >> 2;
    const int ldc = (tid & 3) * 4;

    float acc[2][8][4];
    #pragma unroll
    for (int mt = 0; mt < 2; mt++)
        #pragma unroll
        for (int nt = 0; nt < 8; nt++)
            #pragma unroll
            for (int q = 0; q < 4; q++) acc[mt][nt][q] = 0.f;

    float4 ar[2], br[2];
    #pragma unroll
    for (int h = 0; h < 2; h++) {
        const int row = ldr + h * 64;
        ar[h] = *(const float4*)&A[(size_t)(m0 + row) * K + ldc];
        br[h] = make_float4(0.f, 0.f, 0.f, 0.f);
        if (n0 + row < N)
            br[h] = *(const float4*)&B[(size_t)(n0 + row) * K + ldc];
    }

    for (int k0 = 0; k0 < K; k0 += 16) {
        #pragma unroll
        for (int h = 0; h < 2; h++) {
            const int row = ldr + h * 64;
            float* da = &sA[row * GP + ldc];
            da[0] = f2tf(ar[h].x); da[1] = f2tf(ar[h].y);
            da[2] = f2tf(ar[h].z); da[3] = f2tf(ar[h].w);
            float* db = &sB[row * GP + ldc];
            db[0] = f2tf(br[h].x); db[1] = f2tf(br[h].y);
            db[2] = f2tf(br[h].z); db[3] = f2tf(br[h].w);
        }
        if (k0 + 16 < K) {
            #pragma unroll
            for (int h = 0; h < 2; h++) {
                const int row = ldr + h * 64;
                ar[h] = *(const float4*)&A[(size_t)(m0 + row) * K + k0 + 16 + ldc];
                if (n0 + row < N)
                    br[h] = *(const float4*)&B[(size_t)(n0 + row) * K + k0 + 16 + ldc];
                else
                    br[h] = make_float4(0.f, 0.f, 0.f, 0.f);
            }
        }
        __syncthreads();

        #pragma unroll
        for (int ks = 0; ks < 2; ks++) {
            const int k = ks * 8;
            uint32_t af[2][4], bf[8][2];
            #pragma unroll
            for (int mt = 0; mt < 2; mt++) {
                const int mr = wr * 32 + mt * 16;
                af[mt][0] = __float_as_uint(sA[(mr + g) * GP + k + t]);
                af[mt][1] = __float_as_uint(sA[(mr + g + 8) * GP + k + t]);
                af[mt][2] = __float_as_uint(sA[(mr + g) * GP + k + t + 4]);
                af[mt][3] = __float_as_uint(sA[(mr + g + 8) * GP + k + t + 4]);
            }
            #pragma unroll
            for (int nt = 0; nt < 8; nt++) {
                const int nn = wc * 64 + nt * 8 + g;
                bf[nt][0] = __float_as_uint(sB[nn * GP + k + t]);
                bf[nt][1] = __float_as_uint(sB[nn * GP + k + t + 4]);
            }
            #pragma unroll
            for (int mt = 0; mt < 2; mt++)
                #pragma unroll
                for (int nt = 0; nt < 8; nt++)
                    mma_tf32(acc[mt][nt], af[mt], bf[nt]);
        }
        __syncthreads();
    }

    #pragma unroll
    for (int mt = 0; mt < 2; mt++) {
        #pragma unroll
        for (int rr = 0; rr < 2; rr++) {
            const int m = m0 + wr * 32 + mt * 16 + g + rr * 8;
            #pragma unroll
            for (int nt = 0; nt < 8; nt++) {
                const int n = n0 + wc * 64 + nt * 8 + 2 * t;
                const float v0 = acc[mt][nt][rr * 2 + 0];
                const float v1 = acc[mt][nt][rr * 2 + 1];
                if (MODE == 0) {
                    if (n < N) *(float2*)&C[(size_t)m * N + n] = make_float2(v0, v1);
                } else if (MODE == 1) {
                    const int b = m >> 10, s = m & 1023;
                    const int h = n >> 6, d = n & 63;
                    *(float2*)&C[(((size_t)(b * NH + h)) * SEQ + s) * DH + d] =
                        make_float2(v0, v1);
                } else {
                    *(float2*)&C[(size_t)m * N + n] =
                        make_float2(v0 + bias[n], v1 + bias[n + 1]);
                }
            }
        }
    }
}

// ---------------------------------------------------------------------------
// Fused attention: R4 structure, in-register softmax reductions (no smem RMW),
// V stored untransposed at pitch 72 (conflict-free both sides).
// One CTA per query i; 8 warps = (batch, j-half).
// ---------------------------------------------------------------------------
#define AP 68   // pitch for sQ / sKR / sP
#define VP 72   // pitch for V tile: 72 % 32 == 8 -> AV B-frag reads conflict-free

#define SM_Q   (64 * AP)
#define SM_KV  (4 * 64 * VP)           // KR (pitch AP) / V (pitch VP), time-shared
#define SM_P   (64 * AP)
#define SM_ATTN_FLOATS (SM_Q + SM_KV + SM_P + 2 * 128)
#define SM_ATTN_BYTES  (SM_ATTN_FLOATS * 4)

__global__ __launch_bounds__(256, 2)
void attn_kernel(const float* __restrict__ rel,
                 const float* __restrict__ qb,
                 const float* __restrict__ kb,
                 const float* __restrict__ vb,
                 float* __restrict__ ctx)
{
    extern __shared__ float sm[];
    float* sQ   = sm;                  // [64][AP] tf32 Q rows
    float* sKV  = sQ + SM_Q;           // KR: [b*64+j][AP]+d ; V: [b*64+j][VP]+d
    float* sP   = sKV + SM_KV;         // [row=64][AP]: exp'd tf32 probs
    float* sExM = sP + SM_P;           // [8 warps][16 rows] max exchange
    float* sExS = sExM + 128;          // [8 warps][16 rows] sum exchange

    const int i    = blockIdx.x;
    const int tid  = threadIdx.x;
    const int lane = tid & 31;
    const int w    = tid >> 5;
    const int b    = w >> 1;           // batch
    const int half = w & 1;            // j-half (scores) / d-half (AV)
    const int g    = lane >> 2;
    const int t    = lane & 3;
    const unsigned FULL = 0xffffffffu;

    // Load Q for all 64 (b,h) rows at query i (tf32)
    #pragma unroll
    for (int tix = 0; tix < 16; tix++) {
        const int idx = tix * 256 + tid;
        const int r = idx >> 6, d = idx & 63;
        sQ[r * AP + d] = f2tf(qb[((size_t)r * SEQ + i) * DH + d]);
    }

    // per-warp running softmax state for rows b*16+g and b*16+g+8
    float mr0 = -INFINITY, mr1 = -INFINITY, lr0 = 0.f, lr1 = 0.f;
    float cacc[4][4];
    #pragma unroll
    for (int nt = 0; nt < 4; nt++)
        #pragma unroll
        for (int q = 0; q < 4; q++) cacc[nt][q] = 0.f;

    for (int j0 = 0; j0 < SEQ; j0 += 64) {
        __syncthreads();   // S0: prev tile's AV reads of sKV/sP complete

        // ---- build KR[b][j][d] = tf32(K + rel), pitch AP ----
        #pragma unroll
        for (int tix = 0; tix < 4; tix++) {
            const int idx = tix * 256 + tid;
            const int j  = idx >> 4;
            const int d4 = (idx & 15) * 4;
            const float4 rv = *(const float4*)&rel[((size_t)i * SEQ + j0 + j) * DH + d4];
            if (j0 + 64 < SEQ && (idx & 7) == 0)
                l2_prefetch(&rel[((size_t)i * SEQ + j0 + 64 + j) * DH + d4]);
            #pragma unroll
            for (int bb = 0; bb < 4; bb++) {
                const float4 k4 = *(const float4*)&kb[((size_t)(bb * SEQ) + j0 + j) * DH + d4];
                float4 o;
                o.x = f2tf(k4.x + rv.x); o.y = f2tf(k4.y + rv.y);
                o.z = f2tf(k4.z + rv.z); o.w = f2tf(k4.w + rv.w);
                *(float4*)&sKV[(bb * 64 + j) * AP + d4] = o;
            }
        }
        __syncthreads();   // S1

        // ---- scores MMA: rows b*16+{g,g+8}, cols half*32 + nt*8 + {2t,2t+1} ----
        float pr[4][4];
        #pragma unroll
        for (int nt = 0; nt < 4; nt++)
            #pragma unroll
            for (int q = 0; q < 4; q++) pr[nt][q] = 0.f;

        #pragma unroll
        for (int ks = 0; ks < 8; ks++) {
            const int k = ks * 8;
            uint32_t af[4], bf[2];
            af[0] = __float_as_uint(sQ[(b * 16 + g) * AP + k + t]);
            af[1] = __float_as_uint(sQ[(b * 16 + g + 8) * AP + k + t]);
            af[2] = __float_as_uint(sQ[(b * 16 + g) * AP + k + t + 4]);
            af[3] = __float_as_uint(sQ[(b * 16 + g + 8) * AP + k + t + 4]);
            #pragma unroll
            for (int nt = 0; nt < 4; nt++) {
                const int n = half * 32 + nt * 8 + g;
                bf[0] = __float_as_uint(sKV[(b * 64 + n) * AP + k + t]);
                bf[1] = __float_as_uint(sKV[(b * 64 + n) * AP + k + t + 4]);
                mma_tf32(pr[nt], af, bf);
            }
        }

        // ---- row max in registers (quad reduce) + cross-half exchange ----
        float m0 = -INFINITY, m1 = -INFINITY;
        #pragma unroll
        for (int nt = 0; nt < 4; nt++) {
            m0 = fmaxf(m0, fmaxf(pr[nt][0], pr[nt][1]));
            m1 = fmaxf(m1, fmaxf(pr[nt][2], pr[nt][3]));
        }
        m0 = fmaxf(m0, __shfl_xor_sync(FULL, m0, 1));
        m0 = fmaxf(m0, __shfl_xor_sync(FULL, m0, 2));
        m1 = fmaxf(m1, __shfl_xor_sync(FULL, m1, 1));
        m1 = fmaxf(m1, __shfl_xor_sync(FULL, m1, 2));
        if (t == 0) {
            sExM[w * 16 + g]     = m0;
            sExM[w * 16 + 8 + g] = m1;
        }
        __syncthreads();   // S2: sExM ready; all KR reads done -> V may overwrite

        const float pm0 = sExM[(w ^ 1) * 16 + g];
        const float pm1 = sExM[(w ^ 1) * 16 + 8 + g];
        const float mn0 = fmaxf(mr0, 0.125f * fmaxf(m0, pm0));
        const float mn1 = fmaxf(mr1, 0.125f * fmaxf(m1, pm1));
        const float corr0 = __expf(mr0 - mn0);
        const float corr1 = __expf(mr1 - mn1);
        mr0 = mn0; mr1 = mn1;

        // ---- exp in registers, single tf32 P write, row sums ----
        float s0 = 0.f, s1 = 0.f;
        #pragma unroll
        for (int nt = 0; nt < 4; nt++) {
            float p0 = __expf(0.125f * pr[nt][0] - mn0);
            float p1 = __expf(0.125f * pr[nt][1] - mn0);
            float p2 = __expf(0.125f * pr[nt][2] - mn1);
            float p3 = __expf(0.125f * pr[nt][3] - mn1);
            s0 += p0 + p1; s1 += p2 + p3;
            const int jc = half * 32 + nt * 8 + 2 * t;
            *(float2*)&sP[(b * 16 + g) * AP + jc] =
                make_float2(f2tf(p0), f2tf(p1));
            *(float2*)&sP[(b * 16 + g + 8) * AP + jc] =
                make_float2(f2tf(p2), f2tf(p3));
        }
        s0 += __shfl_xor_sync(FULL, s0, 1);
        s0 += __shfl_xor_sync(FULL, s0, 2);
        s1 += __shfl_xor_sync(FULL, s1, 1);
        s1 += __shfl_xor_sync(FULL, s1, 2);
        if (t == 0) {
            sExS[w * 16 + g]     = s0;
            sExS[w * 16 + 8 + g] = s1;
        }

        // ---- V: gmem [b][j][d] -> sKV[b*64+j][VP]+d (untransposed, float4) ----
        #pragma unroll
        for (int tix = 0; tix < 4; tix++) {
            const int idx = tix * 256 + tid;
            const int j  = idx >> 4;
            const int d4 = (idx & 15) * 4;
            #pragma unroll
            for (int bb = 0; bb < 4; bb++) {
                const float4 v4 = *(const float4*)&vb[((size_t)(bb * SEQ) + j0 + j) * DH + d4];
                float4 o;
                o.x = f2tf(v4.x); o.y = f2tf(v4.y);
                o.z = f2tf(v4.z); o.w = f2tf(v4.w);
                *(float4*)&sKV[(bb * 64 + j) * VP + d4] = o;
            }
        }
        __syncthreads();   // S3: sP, sKV(V), sExS ready

        lr0 = lr0 * corr0 + s0 + sExS[(w ^ 1) * 16 + g];
        lr1 = lr1 * corr1 + s1 + sExS[(w ^ 1) * 16 + 8 + g];

        // ---- rescale ctx + AV MMA: rows b*16+{g,g+8}, N=32 d (half), K=64 j ----
        #pragma unroll
        for (int nt = 0; nt < 4; nt++) {
            cacc[nt][0] *= corr0; cacc[nt][1] *= corr0;
            cacc[nt][2] *= corr1; cacc[nt][3] *= corr1;
        }
        #pragma unroll
        for (int ks = 0; ks < 8; ks++) {
            const int k = ks * 8;   // j within tile
            uint32_t af[4], bf[2];
            af[0] = __float_as_uint(sP[(b * 16 + g) * AP + k + t]);
            af[1] = __float_as_uint(sP[(b * 16 + g + 8) * AP + k + t]);
            af[2] = __float_as_uint(sP[(b * 16 + g) * AP + k + t + 4]);
            af[3] = __float_as_uint(sP[(b * 16 + g + 8) * AP + k + t + 4]);
            #pragma unroll
            for (int nt = 0; nt < 4; nt++) {
                const int n = half * 32 + nt * 8 + g;   // d column
                // B-frag: V[j=k+t][d=n], V[j=k+t+4][d=n] — pitch 72 => bank 8t+g
                bf[0] = __float_as_uint(sKV[(b * 64 + k + t) * VP + n]);
                bf[1] = __float_as_uint(sKV[(b * 64 + k + t + 4) * VP + n]);
                mma_tf32(cacc[nt], af, bf);
            }
        }
    }

    // ---- epilogue: normalize + write ctx [b][i][h*DH + d] ----
    {
        const float inv0 = 1.f / lr0;
        const float inv1 = 1.f / lr1;
        const size_t base = ((size_t)(b * SEQ) + i) * DM;
        #pragma unroll
        for (int nt = 0; nt < 4; nt++) {
            const int d = half * 32 + nt * 8 + 2 * t;
            *(float2*)&ctx[base + g * DH + d] =
                make_float2(cacc[nt][0] * inv0, cacc[nt][1] * inv0);
            *(float2*)&ctx[base + (g + 8) * DH + d] =
                make_float2(cacc[nt][2] * inv1, cacc[nt][3] * inv1);
        }
    }
}

// ---------------------------------------------------------------------------
extern "C" void kernel_launch(void* const* d_in, const int* in_sizes, int n_in,
                              void* d_out, int out_size)
{
    const float* x   = (const float*)d_in[0];
    const float* rel = (const float*)d_in[1];
    const float* Wq  = (const float*)d_in[2];
    const float* Wk  = (const float*)d_in[3];
    const float* Wv  = (const float*)d_in[4];
    const float* Wo  = (const float*)d_in[5];
    const float* bo  = (const float*)d_in[6];
    float* out = (float*)d_out;

    float *qb, *kb, *vb, *ctx;
    cudaGetSymbolAddress((void**)&qb,  g_q);
    cudaGetSymbolAddress((void**)&kb,  g_k);
    cudaGetSymbolAddress((void**)&vb,  g_v);
    cudaGetSymbolAddress((void**)&ctx, g_ctx);

    cudaFuncSetAttribute(attn_kernel,
                         cudaFuncAttributeMaxDynamicSharedMemorySize,
                         SM_ATTN_BYTES);

    const int M = BATCH * SEQ;  // 4096

    // q = x @ Wq^T -> [b,h,s,d]
    {
        dim3 grid(DM / 128, M / 128);
        gemm_tf32<1><<<grid, 256>>>(x, Wq, nullptr, qb, M, DM, DM);
    }
    // k, v = x @ Wk^T, x @ Wv^T -> [b*s, 64]
    {
        dim3 grid(1, M / 128);
        gemm_tf32<0><<<grid, 256>>>(x, Wk, nullptr, kb, M, DH, DM);
        gemm_tf32<0><<<grid, 256>>>(x, Wv, nullptr, vb, M, DH, DM);
    }
    // fused attention
    attn_kernel<<<SEQ, 256, SM_ATTN_BYTES>>>(rel, qb, kb, vb, ctx);

    // out = ctx @ Wo^T + bo
    {
        dim3 grid(DM / 128, M / 128);
        gemm_tf32<2><<<grid, 256>>>(ctx, Wo, bo, out, M, DM, DM);
    }
}

// round 8
// speedup vs baseline: 1.7754x; 1.1209x over previous
#include <cuda_runtime.h>
#include <math.h>
#include <stdint.h>

#define BATCH 4
#define SEQ   1024
#define DM    1024
#define NH    16
#define DH    64

// Scratch (device globals — no allocation allowed)
__device__ float g_q[(size_t)BATCH*NH*SEQ*DH];   // [b*NH+h][s][d]
__device__ float g_k[(size_t)BATCH*SEQ*DH];      // [b*S+s][d]
__device__ float g_v[(size_t)BATCH*SEQ*DH];
__device__ float g_ctx[(size_t)BATCH*SEQ*DM];    // [b*S+s][h*DH+d]

// ---------------------------------------------------------------------------
// TF32 helpers
// ---------------------------------------------------------------------------
__device__ __forceinline__ float f2tf(float x) {
    uint32_t u;
    asm("cvt.rna.tf32.f32 %0, %1;" : "=r"(u) : "f"(x));
    return __uint_as_float(u);
}

__device__ __forceinline__ void mma_tf32(float* c, const uint32_t* a, const uint32_t* b) {
    asm volatile(
        "mma.sync.aligned.m16n8k8.row.col.f32.tf32.tf32.f32 "
        "{%0,%1,%2,%3}, {%4,%5,%6,%7}, {%8,%9}, {%0,%1,%2,%3};\n"
        : "+f"(c[0]), "+f"(c[1]), "+f"(c[2]), "+f"(c[3])
        : "r"(a[0]), "r"(a[1]), "r"(a[2]), "r"(a[3]), "r"(b[0]), "r"(b[1]));
}

// ---------------------------------------------------------------------------
// TF32 GEMM: C = A @ B^T (+bias). A[M,K] rm, B[N,K] rm.
// MODE 0: plain; MODE 1: q permuted write [b,h,s,d]; MODE 2: +bias;
// MODE 3: fused k+v (B rows 0-63 = Wk, 64-127 = Wv passed via `bias`;
//         warp-col 0 writes C(=k), warp-col 1 writes C2(=v), both [M][64]).
// ---------------------------------------------------------------------------
#define GP 20

template<int MODE>
__global__ __launch_bounds__(256, 2)
void gemm_tf32(const float* __restrict__ A, const float* __restrict__ B,
               const float* __restrict__ bias, float* __restrict__ C,
               float* __restrict__ C2, int M, int N, int K)
{
    __shared__ float sA[128 * GP];
    __shared__ float sB[128 * GP];

    const int tid  = threadIdx.x;
    const int lane = tid & 31;
    const int w    = tid >> 5;
    const int wr   = w >> 1;
    const int wc   = w & 1;
    const int g    = lane >> 2;
    const int t    = lane & 3;
    const int m0   = blockIdx.y * 128;
    const int n0   = blockIdx.x * 128;

    const int ldr = tid >> 2;
    const int ldc = (tid & 3) * 4;

    float acc[2][8][4];
    #pragma unroll
    for (int mt = 0; mt < 2; mt++)
        #pragma unroll
        for (int nt = 0; nt < 8; nt++)
            #pragma unroll
            for (int q = 0; q < 4; q++) acc[mt][nt][q] = 0.f;

    float4 ar[2], br[2];
    #pragma unroll
    for (int h = 0; h < 2; h++) {
        const int row = ldr + h * 64;
        ar[h] = *(const float4*)&A[(size_t)(m0 + row) * K + ldc];
        br[h] = make_float4(0.f, 0.f, 0.f, 0.f);
        if (MODE == 3) {
            const float* Bs = (row >= 64) ? bias : B;
            br[h] = *(const float4*)&Bs[(size_t)(row & 63) * K + ldc];
        } else if (n0 + row < N) {
            br[h] = *(const float4*)&B[(size_t)(n0 + row) * K + ldc];
        }
    }

    for (int k0 = 0; k0 < K; k0 += 16) {
        #pragma unroll
        for (int h = 0; h < 2; h++) {
            const int row = ldr + h * 64;
            float* da = &sA[row * GP + ldc];
            da[0] = f2tf(ar[h].x); da[1] = f2tf(ar[h].y);
            da[2] = f2tf(ar[h].z); da[3] = f2tf(ar[h].w);
            float* db = &sB[row * GP + ldc];
            db[0] = f2tf(br[h].x); db[1] = f2tf(br[h].y);
            db[2] = f2tf(br[h].z); db[3] = f2tf(br[h].w);
        }
        if (k0 + 16 < K) {
            #pragma unroll
            for (int h = 0; h < 2; h++) {
                const int row = ldr + h * 64;
                ar[h] = *(const float4*)&A[(size_t)(m0 + row) * K + k0 + 16 + ldc];
                if (MODE == 3) {
                    const float* Bs = (row >= 64) ? bias : B;
                    br[h] = *(const float4*)&Bs[(size_t)(row & 63) * K + k0 + 16 + ldc];
                } else if (n0 + row < N) {
                    br[h] = *(const float4*)&B[(size_t)(n0 + row) * K + k0 + 16 + ldc];
                } else {
                    br[h] = make_float4(0.f, 0.f, 0.f, 0.f);
                }
            }
        }
        __syncthreads();

        #pragma unroll
        for (int ks = 0; ks < 2; ks++) {
            const int k = ks * 8;
            uint32_t af[2][4], bf[8][2];
            #pragma unroll
            for (int mt = 0; mt < 2; mt++) {
                const int mr = wr * 32 + mt * 16;
                af[mt][0] = __float_as_uint(sA[(mr + g) * GP + k + t]);
                af[mt][1] = __float_as_uint(sA[(mr + g + 8) * GP + k + t]);
                af[mt][2] = __float_as_uint(sA[(mr + g) * GP + k + t + 4]);
                af[mt][3] = __float_as_uint(sA[(mr + g + 8) * GP + k + t + 4]);
            }
            #pragma unroll
            for (int nt = 0; nt < 8; nt++) {
                const int nn = wc * 64 + nt * 8 + g;
                bf[nt][0] = __float_as_uint(sB[nn * GP + k + t]);
                bf[nt][1] = __float_as_uint(sB[nn * GP + k + t + 4]);
            }
            #pragma unroll
            for (int mt = 0; mt < 2; mt++)
                #pragma unroll
                for (int nt = 0; nt < 8; nt++)
                    mma_tf32(acc[mt][nt], af[mt], bf[nt]);
        }
        __syncthreads();
    }

    #pragma unroll
    for (int mt = 0; mt < 2; mt++) {
        #pragma unroll
        for (int rr = 0; rr < 2; rr++) {
            const int m = m0 + wr * 32 + mt * 16 + g + rr * 8;
            #pragma unroll
            for (int nt = 0; nt < 8; nt++) {
                const int n = n0 + wc * 64 + nt * 8 + 2 * t;
                const float v0 = acc[mt][nt][rr * 2 + 0];
                const float v1 = acc[mt][nt][rr * 2 + 1];
                if (MODE == 0) {
                    if (n < N) *(float2*)&C[(size_t)m * N + n] = make_float2(v0, v1);
                } else if (MODE == 1) {
                    const int b = m >> 10, s = m & 1023;
                    const int h = n >> 6, d = n & 63;
                    *(float2*)&C[(((size_t)(b * NH + h)) * SEQ + s) * DH + d] =
                        make_float2(v0, v1);
                } else if (MODE == 2) {
                    *(float2*)&C[(size_t)m * N + n] =
                        make_float2(v0 + bias[n], v1 + bias[n + 1]);
                } else {
                    float* dst = wc ? C2 : C;
                    const int nn = nt * 8 + 2 * t;
                    *(float2*)&dst[(size_t)m * 64 + nn] = make_float2(v0, v1);
                }
            }
        }
    }
}

// ---------------------------------------------------------------------------
// Fused attention (R6 structure) + rel register-prefetch one tile ahead,
// Q pre-scaled by 1/sqrt(dh). One CTA per query i; 8 warps = (batch, half).
// ---------------------------------------------------------------------------
#define AP 68   // pitch for sQ / sKR / sP
#define VP 72   // pitch for V tile: 72 % 32 == 8 -> AV B-frag reads conflict-free

#define SM_Q   (64 * AP)
#define SM_KV  (4 * 64 * VP)
#define SM_P   (64 * AP)
#define SM_ATTN_FLOATS (SM_Q + SM_KV + SM_P + 2 * 128)
#define SM_ATTN_BYTES  (SM_ATTN_FLOATS * 4)

__global__ __launch_bounds__(256, 2)
void attn_kernel(const float* __restrict__ rel,
                 const float* __restrict__ qb,
                 const float* __restrict__ kb,
                 const float* __restrict__ vb,
                 float* __restrict__ ctx)
{
    extern __shared__ float sm[];
    float* sQ   = sm;                  // [64][AP] tf32 Q rows (pre-scaled)
    float* sKV  = sQ + SM_Q;           // KR: [b*64+j][AP]+d ; V: [b*64+j][VP]+d
    float* sP   = sKV + SM_KV;         // [row=64][AP]: exp'd tf32 probs
    float* sExM = sP + SM_P;           // [8 warps][16 rows] max exchange
    float* sExS = sExM + 128;          // [8 warps][16 rows] sum exchange

    const int i    = blockIdx.x;
    const int tid  = threadIdx.x;
    const int lane = tid & 31;
    const int w    = tid >> 5;
    const int b    = w >> 1;           // batch
    const int half = w & 1;            // j-half (scores) / d-half (AV)
    const int g    = lane >> 2;
    const int t    = lane & 3;
    const unsigned FULL = 0xffffffffu;

    // Load Q for all 64 (b,h) rows at query i, pre-scaled by 1/8 (tf32)
    #pragma unroll
    for (int tix = 0; tix < 16; tix++) {
        const int idx = tix * 256 + tid;
        const int r = idx >> 6, d = idx & 63;
        sQ[r * AP + d] = f2tf(0.125f * qb[((size_t)r * SEQ + i) * DH + d]);
    }

    // prologue: prefetch tile-0 rel into registers
    float4 relbuf[4];
    #pragma unroll
    for (int tix = 0; tix < 4; tix++) {
        const int idx = tix * 256 + tid;
        const int j  = idx >> 4;
        const int d4 = (idx & 15) * 4;
        relbuf[tix] = *(const float4*)&rel[((size_t)i * SEQ + j) * DH + d4];
    }

    // per-warp running softmax state for rows b*16+g and b*16+g+8
    float mr0 = -INFINITY, mr1 = -INFINITY, lr0 = 0.f, lr1 = 0.f;
    float cacc[4][4];
    #pragma unroll
    for (int nt = 0; nt < 4; nt++)
        #pragma unroll
        for (int q = 0; q < 4; q++) cacc[nt][q] = 0.f;

    for (int j0 = 0; j0 < SEQ; j0 += 64) {
        __syncthreads();   // S0: prev tile's AV reads of sKV/sP complete

        // ---- build KR[b][j][d] = tf32(K + rel) from prefetched rel ----
        #pragma unroll
        for (int tix = 0; tix < 4; tix++) {
            const int idx = tix * 256 + tid;
            const int j  = idx >> 4;
            const int d4 = (idx & 15) * 4;
            const float4 rv = relbuf[tix];
            #pragma unroll
            for (int bb = 0; bb < 4; bb++) {
                const float4 k4 = *(const float4*)&kb[((size_t)(bb * SEQ) + j0 + j) * DH + d4];
                float4 o;
                o.x = f2tf(k4.x + rv.x); o.y = f2tf(k4.y + rv.y);
                o.z = f2tf(k4.z + rv.z); o.w = f2tf(k4.w + rv.w);
                *(float4*)&sKV[(bb * 64 + j) * AP + d4] = o;
            }
        }
        __syncthreads();   // S1

        // ---- prefetch next tile's rel (DRAM latency hidden behind MMA) ----
        if (j0 + 64 < SEQ) {
            #pragma unroll
            for (int tix = 0; tix < 4; tix++) {
                const int idx = tix * 256 + tid;
                const int j  = idx >> 4;
                const int d4 = (idx & 15) * 4;
                relbuf[tix] =
                    *(const float4*)&rel[((size_t)i * SEQ + j0 + 64 + j) * DH + d4];
            }
        }

        // ---- scores MMA: rows b*16+{g,g+8}, cols half*32 + nt*8 + {2t,2t+1} ----
        float pr[4][4];
        #pragma unroll
        for (int nt = 0; nt < 4; nt++)
            #pragma unroll
            for (int q = 0; q < 4; q++) pr[nt][q] = 0.f;

        #pragma unroll
        for (int ks = 0; ks < 8; ks++) {
            const int k = ks * 8;
            uint32_t af[4], bf[2];
            af[0] = __float_as_uint(sQ[(b * 16 + g) * AP + k + t]);
            af[1] = __float_as_uint(sQ[(b * 16 + g + 8) * AP + k + t]);
            af[2] = __float_as_uint(sQ[(b * 16 + g) * AP + k + t + 4]);
            af[3] = __float_as_uint(sQ[(b * 16 + g + 8) * AP + k + t + 4]);
            #pragma unroll
            for (int nt = 0; nt < 4; nt++) {
                const int n = half * 32 + nt * 8 + g;
                bf[0] = __float_as_uint(sKV[(b * 64 + n) * AP + k + t]);
                bf[1] = __float_as_uint(sKV[(b * 64 + n) * AP + k + t + 4]);
                mma_tf32(pr[nt], af, bf);
            }
        }

        // ---- row max in registers (quad reduce) + cross-half exchange ----
        float m0 = -INFINITY, m1 = -INFINITY;
        #pragma unroll
        for (int nt = 0; nt < 4; nt++) {
            m0 = fmaxf(m0, fmaxf(pr[nt][0], pr[nt][1]));
            m1 = fmaxf(m1, fmaxf(pr[nt][2], pr[nt][3]));
        }
        m0 = fmaxf(m0, __shfl_xor_sync(FULL, m0, 1));
        m0 = fmaxf(m0, __shfl_xor_sync(FULL, m0, 2));
        m1 = fmaxf(m1, __shfl_xor_sync(FULL, m1, 1));
        m1 = fmaxf(m1, __shfl_xor_sync(FULL, m1, 2));
        if (t == 0) {
            sExM[w * 16 + g]     = m0;
            sExM[w * 16 + 8 + g] = m1;
        }
        __syncthreads();   // S2: sExM ready; all KR reads done -> V may overwrite

        const float pm0 = sExM[(w ^ 1) * 16 + g];
        const float pm1 = sExM[(w ^ 1) * 16 + 8 + g];
        const float mn0 = fmaxf(mr0, fmaxf(m0, pm0));
        const float mn1 = fmaxf(mr1, fmaxf(m1, pm1));
        const float corr0 = __expf(mr0 - mn0);
        const float corr1 = __expf(mr1 - mn1);
        mr0 = mn0; mr1 = mn1;

        // ---- exp in registers, single tf32 P write, row sums ----
        float s0 = 0.f, s1 = 0.f;
        #pragma unroll
        for (int nt = 0; nt < 4; nt++) {
            float p0 = __expf(pr[nt][0] - mn0);
            float p1 = __expf(pr[nt][1] - mn0);
            float p2 = __expf(pr[nt][2] - mn1);
            float p3 = __expf(pr[nt][3] - mn1);
            s0 += p0 + p1; s1 += p2 + p3;
            const int jc = half * 32 + nt * 8 + 2 * t;
            *(float2*)&sP[(b * 16 + g) * AP + jc] =
                make_float2(f2tf(p0), f2tf(p1));
            *(float2*)&sP[(b * 16 + g + 8) * AP + jc] =
                make_float2(f2tf(p2), f2tf(p3));
        }
        s0 += __shfl_xor_sync(FULL, s0, 1);
        s0 += __shfl_xor_sync(FULL, s0, 2);
        s1 += __shfl_xor_sync(FULL, s1, 1);
        s1 += __shfl_xor_sync(FULL, s1, 2);
        if (t == 0) {
            sExS[w * 16 + g]     = s0;
            sExS[w * 16 + 8 + g] = s1;
        }

        // ---- V: gmem [b][j][d] -> sKV[b*64+j][VP]+d (untransposed, float4) ----
        #pragma unroll
        for (int tix = 0; tix < 4; tix++) {
            const int idx = tix * 256 + tid;
            const int j  = idx >> 4;
            const int d4 = (idx & 15) * 4;
            #pragma unroll
            for (int bb = 0; bb < 4; bb++) {
                const float4 v4 = *(const float4*)&vb[((size_t)(bb * SEQ) + j0 + j) * DH + d4];
                float4 o;
                o.x = f2tf(v4.x); o.y = f2tf(v4.y);
                o.z = f2tf(v4.z); o.w = f2tf(v4.w);
                *(float4*)&sKV[(bb * 64 + j) * VP + d4] = o;
            }
        }
        __syncthreads();   // S3: sP, sKV(V), sExS ready

        lr0 = lr0 * corr0 + s0 + sExS[(w ^ 1) * 16 + g];
        lr1 = lr1 * corr1 + s1 + sExS[(w ^ 1) * 16 + 8 + g];

        // ---- rescale ctx + AV MMA: rows b*16+{g,g+8}, N=32 d (half), K=64 j ----
        #pragma unroll
        for (int nt = 0; nt < 4; nt++) {
            cacc[nt][0] *= corr0; cacc[nt][1] *= corr0;
            cacc[nt][2] *= corr1; cacc[nt][3] *= corr1;
        }
        #pragma unroll
        for (int ks = 0; ks < 8; ks++) {
            const int k = ks * 8;   // j within tile
            uint32_t af[4], bf[2];
            af[0] = __float_as_uint(sP[(b * 16 + g) * AP + k + t]);
            af[1] = __float_as_uint(sP[(b * 16 + g + 8) * AP + k + t]);
            af[2] = __float_as_uint(sP[(b * 16 + g) * AP + k + t + 4]);
            af[3] = __float_as_uint(sP[(b * 16 + g + 8) * AP + k + t + 4]);
            #pragma unroll
            for (int nt = 0; nt < 4; nt++) {
                const int n = half * 32 + nt * 8 + g;   // d column
                bf[0] = __float_as_uint(sKV[(b * 64 + k + t) * VP + n]);
                bf[1] = __float_as_uint(sKV[(b * 64 + k + t + 4) * VP + n]);
                mma_tf32(cacc[nt], af, bf);
            }
        }
    }

    // ---- epilogue: normalize + write ctx [b][i][h*DH + d] ----
    {
        const float inv0 = 1.f / lr0;
        const float inv1 = 1.f / lr1;
        const size_t base = ((size_t)(b * SEQ) + i) * DM;
        #pragma unroll
        for (int nt = 0; nt < 4; nt++) {
            const int d = half * 32 + nt * 8 + 2 * t;
            *(float2*)&ctx[base + g * DH + d] =
                make_float2(cacc[nt][0] * inv0, cacc[nt][1] * inv0);
            *(float2*)&ctx[base + (g + 8) * DH + d] =
                make_float2(cacc[nt][2] * inv1, cacc[nt][3] * inv1);
        }
    }
}

// ---------------------------------------------------------------------------
extern "C" void kernel_launch(void* const* d_in, const int* in_sizes, int n_in,
                              void* d_out, int out_size)
{
    const float* x   = (const float*)d_in[0];
    const float* rel = (const float*)d_in[1];
    const float* Wq  = (const float*)d_in[2];
    const float* Wk  = (const float*)d_in[3];
    const float* Wv  = (const float*)d_in[4];
    const float* Wo  = (const float*)d_in[5];
    const float* bo  = (const float*)d_in[6];
    float* out = (float*)d_out;

    float *qb, *kb, *vb, *ctx;
    cudaGetSymbolAddress((void**)&qb,  g_q);
    cudaGetSymbolAddress((void**)&kb,  g_k);
    cudaGetSymbolAddress((void**)&vb,  g_v);
    cudaGetSymbolAddress((void**)&ctx, g_ctx);

    cudaFuncSetAttribute(attn_kernel,
                         cudaFuncAttributeMaxDynamicSharedMemorySize,
                         SM_ATTN_BYTES);

    const int M = BATCH * SEQ;  // 4096

    // q = x @ Wq^T -> [b,h,s,d]
    {
        dim3 grid(DM / 128, M / 128);
        gemm_tf32<1><<<grid, 256>>>(x, Wq, nullptr, qb, nullptr, M, DM, DM);
    }
    // fused k,v = x @ [Wk;Wv]^T -> g_k, g_v (each [M][64])
    {
        dim3 grid(1, M / 128);
        gemm_tf32<3><<<grid, 256>>>(x, Wk, Wv, kb, vb, M, 128, DM);
    }
    // fused attention
    attn_kernel<<<SEQ, 256, SM_ATTN_BYTES>>>(rel, qb, kb, vb, ctx);

    // out = ctx @ Wo^T + bo
    {
        dim3 grid(DM / 128, M / 128);
        gemm_tf32<2><<<grid, 256>>>(ctx, Wo, bo, out, nullptr, M, DM, DM);
    }
}

// round 9
// speedup vs baseline: 2.0274x; 1.1420x over previous
#include <cuda_runtime.h>
#include <math.h>
#include <stdint.h>

#define BATCH 4
#define SEQ   1024
#define DM    1024
#define NH    16
#define DH    64

// Scratch (device globals — no allocation allowed)
__device__ float g_q[(size_t)BATCH*NH*SEQ*DH];   // [b*NH+h][s][d]
__device__ float g_k[(size_t)BATCH*SEQ*DH];      // [b*S+s][d]
__device__ float g_v[(size_t)BATCH*SEQ*DH];
__device__ float g_ctx[(size_t)BATCH*SEQ*DM];    // [b*S+s][h*DH+d]

// ---------------------------------------------------------------------------
// TF32 helpers
// ---------------------------------------------------------------------------
__device__ __forceinline__ float f2tf(float x) {
    uint32_t u;
    asm("cvt.rna.tf32.f32 %0, %1;" : "=r"(u) : "f"(x));
    return __uint_as_float(u);
}

__device__ __forceinline__ void mma_tf32(float* c, const uint32_t* a, const uint32_t* b) {
    asm volatile(
        "mma.sync.aligned.m16n8k8.row.col.f32.tf32.tf32.f32 "
        "{%0,%1,%2,%3}, {%4,%5,%6,%7}, {%8,%9}, {%0,%1,%2,%3};\n"
        : "+f"(c[0]), "+f"(c[1]), "+f"(c[2]), "+f"(c[3])
        : "r"(a[0]), "r"(a[1]), "r"(a[2]), "r"(a[3]), "r"(b[0]), "r"(b[1]));
}

// ---------------------------------------------------------------------------
// TF32 GEMM, double-buffered smem (1 barrier per k-iter).
// MODE 2: out = A @ Wo^T + bias (plain write)
// MODE 4: fused projections: blocks x<8 compute q = A @ B^T with permuted
//         write [b,h,s,d]; block x==8 computes k,v = A @ [Bk;Bv]^T.
// ---------------------------------------------------------------------------
#define GP 20

template<int MODE>
__global__ __launch_bounds__(256, 2)
void gemm_tf32(const float* __restrict__ A, const float* __restrict__ B,
               const float* __restrict__ Bk, const float* __restrict__ Bv,
               const float* __restrict__ bias,
               float* __restrict__ C, float* __restrict__ Ck, float* __restrict__ Cv,
               int M, int N, int K)
{
    __shared__ float sA[2][128 * GP];
    __shared__ float sB[2][128 * GP];

    const int tid  = threadIdx.x;
    const int lane = tid & 31;
    const int w    = tid >> 5;
    const int wr   = w >> 1;
    const int wc   = w & 1;
    const int g    = lane >> 2;
    const int t    = lane & 3;
    const int m0   = blockIdx.y * 128;
    const bool kv  = (MODE == 4) && (blockIdx.x == 8);
    const int n0   = kv ? 0 : blockIdx.x * 128;

    const int ldr = tid >> 2;        // 0..63
    const int ldc = (tid & 3) * 4;   // 0,4,8,12

    float acc[2][8][4];
    #pragma unroll
    for (int mt = 0; mt < 2; mt++)
        #pragma unroll
        for (int nt = 0; nt < 8; nt++)
            #pragma unroll
            for (int q = 0; q < 4; q++) acc[mt][nt][q] = 0.f;

    float4 ar[2], br[2];

    // prologue: slab 0 -> regs -> smem buf 0; slab 1 -> regs
    #pragma unroll
    for (int h = 0; h < 2; h++) {
        const int row = ldr + h * 64;
        ar[h] = *(const float4*)&A[(size_t)(m0 + row) * K + ldc];
        if (MODE == 4 && kv) {
            const float* Bs = (row >= 64) ? Bv : Bk;
            br[h] = *(const float4*)&Bs[(size_t)(row & 63) * K + ldc];
        } else {
            br[h] = *(const float4*)&B[(size_t)(n0 + row) * K + ldc];
        }
    }
    {
        #pragma unroll
        for (int h = 0; h < 2; h++) {
            const int row = ldr + h * 64;
            float* da = &sA[0][row * GP + ldc];
            da[0] = f2tf(ar[h].x); da[1] = f2tf(ar[h].y);
            da[2] = f2tf(ar[h].z); da[3] = f2tf(ar[h].w);
            float* db = &sB[0][row * GP + ldc];
            db[0] = f2tf(br[h].x); db[1] = f2tf(br[h].y);
            db[2] = f2tf(br[h].z); db[3] = f2tf(br[h].w);
        }
        #pragma unroll
        for (int h = 0; h < 2; h++) {
            const int row = ldr + h * 64;
            ar[h] = *(const float4*)&A[(size_t)(m0 + row) * K + 16 + ldc];
            if (MODE == 4 && kv) {
                const float* Bs = (row >= 64) ? Bv : Bk;
                br[h] = *(const float4*)&Bs[(size_t)(row & 63) * K + 16 + ldc];
            } else {
                br[h] = *(const float4*)&B[(size_t)(n0 + row) * K + 16 + ldc];
            }
        }
    }
    __syncthreads();

    const int nIt = K >> 4;
    for (int it = 0; it < nIt; it++) {
        const int buf = it & 1;
        const float* cA = sA[buf];
        const float* cB = sB[buf];

        // MMA over this slab
        #pragma unroll
        for (int ks = 0; ks < 2; ks++) {
            const int k = ks * 8;
            uint32_t af[2][4], bf[8][2];
            #pragma unroll
            for (int mt = 0; mt < 2; mt++) {
                const int mr = wr * 32 + mt * 16;
                af[mt][0] = __float_as_uint(cA[(mr + g) * GP + k + t]);
                af[mt][1] = __float_as_uint(cA[(mr + g + 8) * GP + k + t]);
                af[mt][2] = __float_as_uint(cA[(mr + g) * GP + k + t + 4]);
                af[mt][3] = __float_as_uint(cA[(mr + g + 8) * GP + k + t + 4]);
            }
            #pragma unroll
            for (int nt = 0; nt < 8; nt++) {
                const int nn = wc * 64 + nt * 8 + g;
                bf[nt][0] = __float_as_uint(cB[nn * GP + k + t]);
                bf[nt][1] = __float_as_uint(cB[nn * GP + k + t + 4]);
            }
            #pragma unroll
            for (int mt = 0; mt < 2; mt++)
                #pragma unroll
                for (int nt = 0; nt < 8; nt++)
                    mma_tf32(acc[mt][nt], af[mt], bf[nt]);
        }

        // stage next slab into the other buffer, prefetch slab after
        if (it + 1 < nIt) {
            float* dA = sA[buf ^ 1];
            float* dB = sB[buf ^ 1];
            #pragma unroll
            for (int h = 0; h < 2; h++) {
                const int row = ldr + h * 64;
                float* da = &dA[row * GP + ldc];
                da[0] = f2tf(ar[h].x); da[1] = f2tf(ar[h].y);
                da[2] = f2tf(ar[h].z); da[3] = f2tf(ar[h].w);
                float* db = &dB[row * GP + ldc];
                db[0] = f2tf(br[h].x); db[1] = f2tf(br[h].y);
                db[2] = f2tf(br[h].z); db[3] = f2tf(br[h].w);
            }
            if (it + 2 < nIt) {
                const int k0 = (it + 2) * 16;
                #pragma unroll
                for (int h = 0; h < 2; h++) {
                    const int row = ldr + h * 64;
                    ar[h] = *(const float4*)&A[(size_t)(m0 + row) * K + k0 + ldc];
                    if (MODE == 4 && kv) {
                        const float* Bs = (row >= 64) ? Bv : Bk;
                        br[h] = *(const float4*)&Bs[(size_t)(row & 63) * K + k0 + ldc];
                    } else {
                        br[h] = *(const float4*)&B[(size_t)(n0 + row) * K + k0 + ldc];
                    }
                }
            }
        }
        __syncthreads();
    }

    // epilogue
    #pragma unroll
    for (int mt = 0; mt < 2; mt++) {
        #pragma unroll
        for (int rr = 0; rr < 2; rr++) {
            const int m = m0 + wr * 32 + mt * 16 + g + rr * 8;
            #pragma unroll
            for (int nt = 0; nt < 8; nt++) {
                const int n = n0 + wc * 64 + nt * 8 + 2 * t;
                const float v0 = acc[mt][nt][rr * 2 + 0];
                const float v1 = acc[mt][nt][rr * 2 + 1];
                if (MODE == 2) {
                    *(float2*)&C[(size_t)m * N + n] =
                        make_float2(v0 + bias[n], v1 + bias[n + 1]);
                } else if (MODE == 4 && !kv) {
                    const int b = m >> 10, s = m & 1023;
                    const int h = n >> 6, d = n & 63;
                    *(float2*)&C[(((size_t)(b * NH + h)) * SEQ + s) * DH + d] =
                        make_float2(v0, v1);
                } else {
                    float* dst = wc ? Cv : Ck;
                    const int nn = nt * 8 + 2 * t;
                    *(float2*)&dst[(size_t)m * 64 + nn] = make_float2(v0, v1);
                }
            }
        }
    }
}

// ---------------------------------------------------------------------------
// Fused attention (R7 structure). f2tf dropped on Q/KR (softmax-safe),
// kept (rna) on P and V. One CTA per query i; 8 warps = (batch, half).
// ---------------------------------------------------------------------------
#define AP 68   // pitch for sQ / sKR / sP
#define VP 72   // pitch for V tile: 72 % 32 == 8 -> AV B-frag reads conflict-free

#define SM_Q   (64 * AP)
#define SM_KV  (4 * 64 * VP)
#define SM_P   (64 * AP)
#define SM_ATTN_FLOATS (SM_Q + SM_KV + SM_P + 2 * 128)
#define SM_ATTN_BYTES  (SM_ATTN_FLOATS * 4)

__global__ __launch_bounds__(256, 2)
void attn_kernel(const float* __restrict__ rel,
                 const float* __restrict__ qb,
                 const float* __restrict__ kb,
                 const float* __restrict__ vb,
                 float* __restrict__ ctx)
{
    extern __shared__ float sm[];
    float* sQ   = sm;                  // [64][AP] Q rows (pre-scaled)
    float* sKV  = sQ + SM_Q;           // KR: [b*64+j][AP]+d ; V: [b*64+j][VP]+d
    float* sP   = sKV + SM_KV;         // [row=64][AP]: exp'd tf32 probs
    float* sExM = sP + SM_P;           // [8 warps][16 rows] max exchange
    float* sExS = sExM + 128;          // [8 warps][16 rows] sum exchange

    const int i    = blockIdx.x;
    const int tid  = threadIdx.x;
    const int lane = tid & 31;
    const int w    = tid >> 5;
    const int b    = w >> 1;           // batch
    const int half = w & 1;            // j-half (scores) / d-half (AV)
    const int g    = lane >> 2;
    const int t    = lane & 3;
    const unsigned FULL = 0xffffffffu;

    // Load Q for all 64 (b,h) rows at query i, pre-scaled by 1/8
    #pragma unroll
    for (int tix = 0; tix < 16; tix++) {
        const int idx = tix * 256 + tid;
        const int r = idx >> 6, d = idx & 63;
        sQ[r * AP + d] = 0.125f * qb[((size_t)r * SEQ + i) * DH + d];
    }

    // prologue: prefetch tile-0 rel into registers
    float4 relbuf[4];
    #pragma unroll
    for (int tix = 0; tix < 4; tix++) {
        const int idx = tix * 256 + tid;
        const int j  = idx >> 4;
        const int d4 = (idx & 15) * 4;
        relbuf[tix] = *(const float4*)&rel[((size_t)i * SEQ + j) * DH + d4];
    }

    // per-warp running softmax state for rows b*16+g and b*16+g+8
    float mr0 = -INFINITY, mr1 = -INFINITY, lr0 = 0.f, lr1 = 0.f;
    float cacc[4][4];
    #pragma unroll
    for (int nt = 0; nt < 4; nt++)
        #pragma unroll
        for (int q = 0; q < 4; q++) cacc[nt][q] = 0.f;

    for (int j0 = 0; j0 < SEQ; j0 += 64) {
        __syncthreads();   // S0: prev tile's AV reads of sKV/sP complete

        // ---- build KR[b][j][d] = K + rel (raw fp32; MMA truncates) ----
        #pragma unroll
        for (int tix = 0; tix < 4; tix++) {
            const int idx = tix * 256 + tid;
            const int j  = idx >> 4;
            const int d4 = (idx & 15) * 4;
            const float4 rv = relbuf[tix];
            #pragma unroll
            for (int bb = 0; bb < 4; bb++) {
                const float4 k4 = *(const float4*)&kb[((size_t)(bb * SEQ) + j0 + j) * DH + d4];
                float4 o;
                o.x = k4.x + rv.x; o.y = k4.y + rv.y;
                o.z = k4.z + rv.z; o.w = k4.w + rv.w;
                *(float4*)&sKV[(bb * 64 + j) * AP + d4] = o;
            }
        }
        __syncthreads();   // S1

        // ---- prefetch next tile's rel (DRAM latency hidden behind MMA) ----
        if (j0 + 64 < SEQ) {
            #pragma unroll
            for (int tix = 0; tix < 4; tix++) {
                const int idx = tix * 256 + tid;
                const int j  = idx >> 4;
                const int d4 = (idx & 15) * 4;
                relbuf[tix] =
                    *(const float4*)&rel[((size_t)i * SEQ + j0 + 64 + j) * DH + d4];
            }
        }

        // ---- scores MMA: rows b*16+{g,g+8}, cols half*32 + nt*8 + {2t,2t+1} ----
        float pr[4][4];
        #pragma unroll
        for (int nt = 0; nt < 4; nt++)
            #pragma unroll
            for (int q = 0; q < 4; q++) pr[nt][q] = 0.f;

        #pragma unroll
        for (int ks = 0; ks < 8; ks++) {
            const int k = ks * 8;
            uint32_t af[4], bf[2];
            af[0] = __float_as_uint(sQ[(b * 16 + g) * AP + k + t]);
            af[1] = __float_as_uint(sQ[(b * 16 + g + 8) * AP + k + t]);
            af[2] = __float_as_uint(sQ[(b * 16 + g) * AP + k + t + 4]);
            af[3] = __float_as_uint(sQ[(b * 16 + g + 8) * AP + k + t + 4]);
            #pragma unroll
            for (int nt = 0; nt < 4; nt++) {
                const int n = half * 32 + nt * 8 + g;
                bf[0] = __float_as_uint(sKV[(b * 64 + n) * AP + k + t]);
                bf[1] = __float_as_uint(sKV[(b * 64 + n) * AP + k + t + 4]);
                mma_tf32(pr[nt], af, bf);
            }
        }

        // ---- row max in registers (quad reduce) + cross-half exchange ----
        float m0 = -INFINITY, m1 = -INFINITY;
        #pragma unroll
        for (int nt = 0; nt < 4; nt++) {
            m0 = fmaxf(m0, fmaxf(pr[nt][0], pr[nt][1]));
            m1 = fmaxf(m1, fmaxf(pr[nt][2], pr[nt][3]));
        }
        m0 = fmaxf(m0, __shfl_xor_sync(FULL, m0, 1));
        m0 = fmaxf(m0, __shfl_xor_sync(FULL, m0, 2));
        m1 = fmaxf(m1, __shfl_xor_sync(FULL, m1, 1));
        m1 = fmaxf(m1, __shfl_xor_sync(FULL, m1, 2));
        if (t == 0) {
            sExM[w * 16 + g]     = m0;
            sExM[w * 16 + 8 + g] = m1;
        }
        __syncthreads();   // S2: sExM ready; all KR reads done -> V may overwrite

        const float pm0 = sExM[(w ^ 1) * 16 + g];
        const float pm1 = sExM[(w ^ 1) * 16 + 8 + g];
        const float mn0 = fmaxf(mr0, fmaxf(m0, pm0));
        const float mn1 = fmaxf(mr1, fmaxf(m1, pm1));
        const float corr0 = __expf(mr0 - mn0);
        const float corr1 = __expf(mr1 - mn1);
        mr0 = mn0; mr1 = mn1;

        // ---- exp in registers, single tf32 P write, row sums ----
        float s0 = 0.f, s1 = 0.f;
        #pragma unroll
        for (int nt = 0; nt < 4; nt++) {
            float p0 = __expf(pr[nt][0] - mn0);
            float p1 = __expf(pr[nt][1] - mn0);
            float p2 = __expf(pr[nt][2] - mn1);
            float p3 = __expf(pr[nt][3] - mn1);
            s0 += p0 + p1; s1 += p2 + p3;
            const int jc = half * 32 + nt * 8 + 2 * t;
            *(float2*)&sP[(b * 16 + g) * AP + jc] =
                make_float2(f2tf(p0), f2tf(p1));
            *(float2*)&sP[(b * 16 + g + 8) * AP + jc] =
                make_float2(f2tf(p2), f2tf(p3));
        }
        s0 += __shfl_xor_sync(FULL, s0, 1);
        s0 += __shfl_xor_sync(FULL, s0, 2);
        s1 += __shfl_xor_sync(FULL, s1, 1);
        s1 += __shfl_xor_sync(FULL, s1, 2);
        if (t == 0) {
            sExS[w * 16 + g]     = s0;
            sExS[w * 16 + 8 + g] = s1;
        }

        // ---- V: gmem [b][j][d] -> sKV[b*64+j][VP]+d (rna tf32, float4) ----
        #pragma unroll
        for (int tix = 0; tix < 4; tix++) {
            const int idx = tix * 256 + tid;
            const int j  = idx >> 4;
            const int d4 = (idx & 15) * 4;
            #pragma unroll
            for (int bb = 0; bb < 4; bb++) {
                const float4 v4 = *(const float4*)&vb[((size_t)(bb * SEQ) + j0 + j) * DH + d4];
                float4 o;
                o.x = f2tf(v4.x); o.y = f2tf(v4.y);
                o.z = f2tf(v4.z); o.w = f2tf(v4.w);
                *(float4*)&sKV[(bb * 64 + j) * VP + d4] = o;
            }
        }
        __syncthreads();   // S3: sP, sKV(V), sExS ready

        lr0 = lr0 * corr0 + s0 + sExS[(w ^ 1) * 16 + g];
        lr1 = lr1 * corr1 + s1 + sExS[(w ^ 1) * 16 + 8 + g];

        // ---- rescale ctx + AV MMA: rows b*16+{g,g+8}, N=32 d (half), K=64 j ----
        #pragma unroll
        for (int nt = 0; nt < 4; nt++) {
            cacc[nt][0] *= corr0; cacc[nt][1] *= corr0;
            cacc[nt][2] *= corr1; cacc[nt][3] *= corr1;
        }
        #pragma unroll
        for (int ks = 0; ks < 8; ks++) {
            const int k = ks * 8;   // j within tile
            uint32_t af[4], bf[2];
            af[0] = __float_as_uint(sP[(b * 16 + g) * AP + k + t]);
            af[1] = __float_as_uint(sP[(b * 16 + g + 8) * AP + k + t]);
            af[2] = __float_as_uint(sP[(b * 16 + g) * AP + k + t + 4]);
            af[3] = __float_as_uint(sP[(b * 16 + g + 8) * AP + k + t + 4]);
            #pragma unroll
            for (int nt = 0; nt < 4; nt++) {
                const int n = half * 32 + nt * 8 + g;   // d column
                bf[0] = __float_as_uint(sKV[(b * 64 + k + t) * VP + n]);
                bf[1] = __float_as_uint(sKV[(b * 64 + k + t + 4) * VP + n]);
                mma_tf32(cacc[nt], af, bf);
            }
        }
    }

    // ---- epilogue: normalize + write ctx [b][i][h*DH + d] ----
    {
        const float inv0 = 1.f / lr0;
        const float inv1 = 1.f / lr1;
        const size_t base = ((size_t)(b * SEQ) + i) * DM;
        #pragma unroll
        for (int nt = 0; nt < 4; nt++) {
            const int d = half * 32 + nt * 8 + 2 * t;
            *(float2*)&ctx[base + g * DH + d] =
                make_float2(cacc[nt][0] * inv0, cacc[nt][1] * inv0);
            *(float2*)&ctx[base + (g + 8) * DH + d] =
                make_float2(cacc[nt][2] * inv1, cacc[nt][3] * inv1);
        }
    }
}

// ---------------------------------------------------------------------------
extern "C" void kernel_launch(void* const* d_in, const int* in_sizes, int n_in,
                              void* d_out, int out_size)
{
    const float* x   = (const float*)d_in[0];
    const float* rel = (const float*)d_in[1];
    const float* Wq  = (const float*)d_in[2];
    const float* Wk  = (const float*)d_in[3];
    const float* Wv  = (const float*)d_in[4];
    const float* Wo  = (const float*)d_in[5];
    const float* bo  = (const float*)d_in[6];
    float* out = (float*)d_out;

    float *qb, *kb, *vb, *ctx;
    cudaGetSymbolAddress((void**)&qb,  g_q);
    cudaGetSymbolAddress((void**)&kb,  g_k);
    cudaGetSymbolAddress((void**)&vb,  g_v);
    cudaGetSymbolAddress((void**)&ctx, g_ctx);

    cudaFuncSetAttribute(attn_kernel,
                         cudaFuncAttributeMaxDynamicSharedMemorySize,
                         SM_ATTN_BYTES);

    const int M = BATCH * SEQ;  // 4096

    // fused q|k|v projections: blocks x=0..7 -> q (permuted), x=8 -> k,v
    {
        dim3 grid(9, M / 128);
        gemm_tf32<4><<<grid, 256>>>(x, Wq, Wk, Wv, nullptr,
                                    qb, kb, vb, M, DM, DM);
    }
    // fused attention
    attn_kernel<<<SEQ, 256, SM_ATTN_BYTES>>>(rel, qb, kb, vb, ctx);

    // out = ctx @ Wo^T + bo
    {
        dim3 grid(8, M / 128);
        gemm_tf32<2><<<grid, 256>>>(ctx, Wo, nullptr, nullptr, bo,
                                    out, nullptr, nullptr, M, DM, DM);
    }
}